// round 9
// baseline (speedup 1.0000x reference)
#include <cuda_runtime.h>
#include <cuda_bf16.h>
#include <cstdint>

// Problem shape (fixed by the dataset)
#define BB 64
#define CC 256
#define HH 80
#define WW 80
#define NN 100
#define IMG 640.0f

#define NPLANES (BB * CC)          // 16384 planes
#define PLANE_ELEMS (HH * WW)      // 6400 floats
#define PSTRIDE 84                 // padded smem row stride (floats)
#define PBUF (HH * PSTRIDE)        // 6720 floats per slot (26.88 KB)
#define NG 4                       // groups per CTA
#define GWARPS 8                   // warps per group: 5 loader + 3 compute
#define GRID 152                   // persistent, one CTA per SM
#define TPB (NG * GWARPS * 32)     // 1024 threads
#define STRIDEP (GRID * NG)        // 608 groups chip-wide
#define PF 16                      // loader rotating-prefetch depth (regs)
#define SPLITROW 39                // top half rows [0,39), bottom [39,80)

__device__ __forceinline__ void named_bar(int id, int count) {
    asm volatile("bar.sync %0, %1;" :: "r"(id), "r"(count) : "memory");
}

// Fused GMEM load + column partial-cumsum into padded smem buffer.
// 160 lanes: lane<80 -> column lane, rows [0,39); lane>=80 -> column lane-80,
// rows [39,80) (partial sums, compensated in pass 3). PF-deep rotating
// register prefetch; pure FADD accumulation (no shuffles).
__device__ __forceinline__ void load_colscan(const float* __restrict__ plane,
                                             float* __restrict__ S, int ll) {
    const int half = (ll >= WW);
    const int col  = half ? (ll - WW) : ll;
    const int y0   = half ? SPLITROW : 0;
    const int nrows = half ? (HH - SPLITROW) : SPLITROW;   // 41 / 39

    float buf[PF];
    #pragma unroll
    for (int d = 0; d < PF; ++d)
        buf[d] = __ldg(plane + (y0 + d) * WW + col);

    float acc = 0.0f;
    #pragma unroll
    for (int k = 0; k < HH - SPLITROW; ++k) {   // 41 iters, top half predicated
        if (k < nrows) {
            float v = buf[k % PF];
            const int kn = k + PF;
            if (kn < nrows)
                buf[k % PF] = __ldg(plane + (y0 + kn) * WW + col);
            acc += v;
            S[(y0 + k) * PSTRIDE + col] = acc;
        }
    }
}

__global__ __launch_bounds__(TPB, 1)
void roi_pool_kernel(const float* __restrict__ fmap,
                     const float* __restrict__ boxes,
                     float* __restrict__ out)
{
    extern __shared__ __align__(16) float P[];   // [NG][2][PBUF] = 215 KB

    const int tid  = threadIdx.x;
    const int wid  = tid >> 5;
    const int lane = tid & 31;
    const int bid  = blockIdx.x;

    const int g  = wid / GWARPS;             // group 0..3
    const int wg = wid % GWARPS;             // warp in group 0..7
    const bool loader = (wg < 5);
    const int ll = wg * 32 + lane;           // loader lane 0..159
    const int ct = (wg - 5) * 32 + lane;     // compute lane 0..95

    float* const B0 = P + (size_t)(g * 2) * PBUF;
    float* const B1 = B0 + PBUF;
    const int G = bid * NG + g;              // global group id 0..607

    // Prologue: loaders fill slot 0 for plane G.
    if (loader && G < NPLANES)
        load_colscan(fmap + (size_t)G * PLANE_ELEMS, B0, ll);

    for (int it = 0; ; ++it) {
        const int p = G + it * STRIDEP;
        if (p >= NPLANES) break;

        // slot(it&1) ready (written last iter / prologue); slot((it+1)&1)
        // free (compute finished it at it-1). bar.sync drains pending STS.
        named_bar(1 + g, GWARPS * 32);

        if (loader) {
            const int pn = p + STRIDEP;
            if (pn < NPLANES)
                load_colscan(fmap + (size_t)pn * PLANE_ELEMS,
                             ((it + 1) & 1) ? B1 : B0, ll);
        } else {
            float* S = (it & 1) ? B1 : B0;

            // ===== Pass 2: row cumsum (axis x), float4, in place. =====
            // ALL 80 rows are independent (bottom rows scan partial colsums;
            // the missing top-block contribution is added in pass 3).
            // Row stride 21 float4 -> conflict-free phasing.
            if (ct < HH) {
                float4* row = reinterpret_cast<float4*>(S + ct * PSTRIDE);
                float acc = 0.0f;
                #pragma unroll
                for (int q = 0; q < WW / 4; ++q) {
                    float4 v4 = row[q];
                    v4.x += acc;
                    v4.y += v4.x;
                    v4.z += v4.y;
                    v4.w += v4.z;
                    acc = v4.w;
                    row[q] = v4;
                }
            }
            named_bar(1 + NG + g, 96);   // compute-warps-only barrier

            // ===== Pass 3: 100 boxes (2 rounds over 96 lanes). =====
            // Two-level lookup: true inclusive integral at (yr, xc) is
            // stored[yr][xc] + (yr >= SPLITROW ? stored[SPLITROW-1][xc] : 0).
            const int b = p / CC;
            const int c = p % CC;
            #pragma unroll
            for (int r0 = 0; r0 < 2; ++r0) {
                const int n = ct + r0 * 96;
                if (n < NN) {
                    float4 bx = reinterpret_cast<const float4*>(boxes)[b * NN + n];
                    // Reference math exactly: (coord/640)*80 fp32 RN, int
                    // truncation (non-negative => floor), clip to [0, dim].
                    int x1 = (int)__fmul_rn(__fdiv_rn(bx.x, IMG), (float)WW);
                    int y1 = (int)__fmul_rn(__fdiv_rn(bx.y, IMG), (float)HH);
                    int x2 = (int)__fmul_rn(__fdiv_rn(bx.z, IMG), (float)WW);
                    int y2 = (int)__fmul_rn(__fdiv_rn(bx.w, IMG), (float)HH);
                    x1 = min(max(x1, 0), WW);
                    y1 = min(max(y1, 0), HH);
                    x2 = min(max(x2, 0), WW);
                    y2 = min(max(y2, 0), HH);

                    const int dy = y2 - y1;
                    const int dx = x2 - x1;
                    float r = 0.0f;
                    if (dy > 0 && dx > 0) {
                        auto val = [&](int yr, int xc) -> float {
                            float s = S[yr * PSTRIDE + xc];
                            if (yr >= SPLITROW)
                                s += S[(SPLITROW - 1) * PSTRIDE + xc];
                            return s;
                        };
                        float s22 = val(y2 - 1, x2 - 1);
                        float s12 = (y1 > 0) ? val(y1 - 1, x2 - 1) : 0.0f;
                        float s21 = (x1 > 0) ? val(y2 - 1, x1 - 1) : 0.0f;
                        float s11 = (y1 > 0 && x1 > 0) ? val(y1 - 1, x1 - 1) : 0.0f;
                        r = __fdiv_rn(s22 - s12 - s21 + s11, (float)(dy * dx));
                    }
                    out[((size_t)b * NN + n) * CC + c] = r;
                }
            }
        }
        // Top-of-loop group barrier orders: compute reads of slot(it&1) before
        // loaders overwrite it at it+2; loader writes of slot((it+1)&1) before
        // compute reads them at it+1.
    }
}

extern "C" void kernel_launch(void* const* d_in, const int* in_sizes, int n_in,
                              void* d_out, int out_size)
{
    const float* fmap  = (const float*)d_in[0];   // [64,256,80,80]
    const float* boxes = (const float*)d_in[1];   // [64,100,4]
    float* out = (float*)d_out;                   // [64,100,256]

    const int smem_bytes = NG * 2 * PBUF * sizeof(float);   // 215040
    cudaFuncSetAttribute(roi_pool_kernel,
                         cudaFuncAttributeMaxDynamicSharedMemorySize,
                         smem_bytes);

    roi_pool_kernel<<<GRID, TPB, smem_bytes>>>(fmap, boxes, out);
}